// round 9
// baseline (speedup 1.0000x reference)
#include <cuda_runtime.h>
#include <cuda_bf16.h>
#include <cstdint>
#include <math.h>

// Problem dims (fixed)
#define NB   8
#define NS   1024
#define NH   16
#define NDK  64
#define FDEC 1024
#define FD   16
#define KINR 784
#define KP   1024
#define MROWS (NB*NS)   // 8192

// ---------------- scratch (static __device__, no allocation) ----------------
__device__ float g_x  [MROWS * FDEC];
__device__ float g_q  [MROWS * FDEC];
__device__ float g_k  [MROWS * FDEC];
__device__ float g_v  [MROWS * FDEC];
__device__ float g_o  [MROWS * FDEC];
__device__ float g_x2 [MROWS * FDEC];

// int8 2-digit quantized operands + per-row scales
__device__ int8_t g_xc1[MROWS * KP], g_xc2[MROWS * KP];
__device__ int8_t g_xn1[MROWS * KP], g_xn2[MROWS * KP];
__device__ int8_t g_oq1[MROWS * KP], g_oq2[MROWS * KP];
__device__ int8_t g_wd1[FDEC * KP], g_wd2[FDEC * KP];
__device__ int8_t g_wq1[FDEC * KP], g_wq2[FDEC * KP];
__device__ int8_t g_wk1[FDEC * KP], g_wk2[FDEC * KP];
__device__ int8_t g_wv1[FDEC * KP], g_wv2[FDEC * KP];
__device__ int8_t g_wo1[FDEC * KP], g_wo2[FDEC * KP];
__device__ float g_sxc[MROWS], g_sxn[MROWS], g_so[MROWS];
__device__ float g_swd[FDEC], g_swq[FDEC], g_swk[FDEC], g_swv[FDEC], g_swo[FDEC];

// ---------------- PTX helpers ------------------------------------------------
__device__ __forceinline__ uint32_t smem_u32(const void* p) {
    uint32_t a;
    asm("{ .reg .u64 t; cvta.to.shared.u64 t, %1; cvt.u32.u64 %0, t; }" : "=r"(a) : "l"(p));
    return a;
}

#define MMA_S8(C, A, B0, B1) \
    asm volatile("mma.sync.aligned.m16n8k32.row.col.s32.s8.s8.s32 " \
        "{%0,%1,%2,%3},{%4,%5,%6,%7},{%8,%9},{%0,%1,%2,%3};" \
        : "+r"((C)[0]), "+r"((C)[1]), "+r"((C)[2]), "+r"((C)[3]) \
        : "r"((A)[0]), "r"((A)[1]), "r"((A)[2]), "r"((A)[3]), "r"(B0), "r"(B1))

#define MMA_TF32(C, A, B0, B1) \
    asm volatile("mma.sync.aligned.m16n8k8.row.col.f32.tf32.tf32.f32 " \
        "{%0,%1,%2,%3},{%4,%5,%6,%7},{%8,%9},{%0,%1,%2,%3};" \
        : "+f"((C)[0]), "+f"((C)[1]), "+f"((C)[2]), "+f"((C)[3]) \
        : "r"((A)[0]), "r"((A)[1]), "r"((A)[2]), "r"((A)[3]), "r"(B0), "r"(B1))

__device__ __forceinline__ uint32_t to_tf32(float f) {
    uint32_t r;
    asm("cvt.rna.tf32.f32 %0, %1;" : "=r"(r) : "f"(f));
    return r;
}

__device__ __forceinline__ void cpa16(uint32_t dst, const void* src) {
    asm volatile("cp.async.cg.shared.global [%0], [%1], 16;" :: "r"(dst), "l"(src));
}
#define CP_COMMIT() asm volatile("cp.async.commit_group;" ::: "memory")
#define CP_WAIT(n)  asm volatile("cp.async.wait_group %0;" :: "n"(n) : "memory")

// ---------------- reductions --------------------------------------------------
__device__ __forceinline__ float blockReduce(float val, float* sh)
{
    __syncthreads();
    int lane = threadIdx.x & 31, wid = threadIdx.x >> 5;
    #pragma unroll
    for (int o = 16; o; o >>= 1) val += __shfl_xor_sync(0xffffffffu, val, o);
    if (lane == 0) sh[wid] = val;
    __syncthreads();
    if (wid == 0) {
        val = (lane < 8) ? sh[lane] : 0.f;
        #pragma unroll
        for (int o = 4; o; o >>= 1) val += __shfl_xor_sync(0xffffffffu, val, o);
        if (lane == 0) sh[0] = val;
    }
    __syncthreads();
    return sh[0];
}

__device__ __forceinline__ float blockReduceMax(float val, float* sh)
{
    __syncthreads();
    int lane = threadIdx.x & 31, wid = threadIdx.x >> 5;
    #pragma unroll
    for (int o = 16; o; o >>= 1) val = fmaxf(val, __shfl_xor_sync(0xffffffffu, val, o));
    if (lane == 0) sh[wid] = val;
    __syncthreads();
    if (wid == 0) {
        val = (lane < 8) ? sh[lane] : 0.f;
        #pragma unroll
        for (int o = 4; o; o >>= 1) val = fmaxf(val, __shfl_xor_sync(0xffffffffu, val, o));
        if (lane == 0) sh[0] = val;
    }
    __syncthreads();
    return sh[0];
}

// quantize 4 values + write (cols c0..c0+3 of row)
__device__ __forceinline__ void quant_store4(
    const float* v, float inv127, int8_t* q1, int8_t* q2, size_t base)
{
    char b1[4], b2[4];
    #pragma unroll
    for (int j = 0; j < 4; j++) {
        float xs = v[j] * inv127;
        int d1 = __float2int_rn(xs);
        d1 = max(-127, min(127, d1));
        int d2 = __float2int_rn((xs - (float)d1) * 128.0f);
        d2 = max(-127, min(127, d2));
        b1[j] = (char)d1; b2[j] = (char)d2;
    }
    *(char4*)(q1 + base) = make_char4(b1[0], b1[1], b1[2], b1[3]);
    *(char4*)(q2 + base) = make_char4(b2[0], b2[1], b2[2], b2[3]);
}

// ---------------- generic row quantizer (src [R][Ksrc] -> padded 1024) -------
__global__ void __launch_bounds__(256) quant_k(
    const float* __restrict__ src, int Ksrc,
    int8_t* __restrict__ q1, int8_t* __restrict__ q2, float* __restrict__ sc)
{
    __shared__ float red[32];
    const int row = blockIdx.x, t = threadIdx.x, c0 = t * 4;
    float v[4] = {0.f, 0.f, 0.f, 0.f};
    if (c0 + 3 < Ksrc) {
        float4 f = *(const float4*)(src + (size_t)row * Ksrc + c0);
        v[0] = f.x; v[1] = f.y; v[2] = f.z; v[3] = f.w;
    }
    float m = fmaxf(fmaxf(fabsf(v[0]), fabsf(v[1])), fmaxf(fabsf(v[2]), fabsf(v[3])));
    m = blockReduceMax(m, red);
    float inv127 = (m > 0.f) ? 127.0f / m : 0.f;
    quant_store4(v, inv127, q1, q2, (size_t)row * KP + c0);
    if (t == 0) sc[row] = (m > 0.f) ? m / 127.0f : 1.0f;
}

// ---------------- fused concat + quant ---------------------------------------
__global__ void __launch_bounds__(256) concat_quant_k(
    const float* __restrict__ r, const float* __restrict__ z,
    int8_t* __restrict__ q1, int8_t* __restrict__ q2, float* __restrict__ sc)
{
    __shared__ float red[32];
    const int m = blockIdx.x, t = threadIdx.x, c0 = t * 4;
    const int b = m >> 10;
    float v[4];
    #pragma unroll
    for (int j = 0; j < 4; j++) {
        int c = c0 + j;
        v[j] = (c < 16) ? r[m * 16 + c] : (c < KINR) ? z[b * 768 + (c - 16)] : 0.f;
    }
    float mx = fmaxf(fmaxf(fabsf(v[0]), fabsf(v[1])), fmaxf(fabsf(v[2]), fabsf(v[3])));
    mx = blockReduceMax(mx, red);
    float inv127 = (mx > 0.f) ? 127.0f / mx : 0.f;
    quant_store4(v, inv127, q1, q2, (size_t)m * KP + c0);
    if (t == 0) sc[m] = (mx > 0.f) ? mx / 127.0f : 1.0f;
}

// ---------------- fused LayerNorm + quant ------------------------------------
__global__ void __launch_bounds__(256) ln_quant_k(
    const float* __restrict__ x, const float* __restrict__ g,
    const float* __restrict__ beta,
    int8_t* __restrict__ q1, int8_t* __restrict__ q2, float* __restrict__ sc)
{
    __shared__ float red[32];
    const int row = blockIdx.x, t = threadIdx.x;
    float4 v = ((const float4*)(x + (size_t)row * 1024))[t];
    float s = blockReduce(v.x + v.y + v.z + v.w, red);
    float mean = s * (1.0f / 1024.0f);
    float dx = v.x - mean, dy = v.y - mean, dz = v.z - mean, dw = v.w - mean;
    float s2 = blockReduce(dx*dx + dy*dy + dz*dz + dw*dw, red);
    float inv = rsqrtf(s2 * (1.0f / 1024.0f) + 1e-6f);
    float4 gg = ((const float4*)g)[t];
    float4 bb = ((const float4*)beta)[t];
    float o[4];
    o[0] = gg.x * dx * inv + bb.x;
    o[1] = gg.y * dy * inv + bb.y;
    o[2] = gg.z * dz * inv + bb.z;
    o[3] = gg.w * dw * inv + bb.w;
    float mx = fmaxf(fmaxf(fabsf(o[0]), fabsf(o[1])), fmaxf(fabsf(o[2]), fabsf(o[3])));
    mx = blockReduceMax(mx, red);
    float inv127 = (mx > 0.f) ? 127.0f / mx : 0.f;
    quant_store4(o, inv127, q1, q2, (size_t)row * KP + t * 4);
    if (t == 0) sc[row] = (mx > 0.f) ? mx / 127.0f : 1.0f;
}

// ---------------- int8 ozIMMU GEMM -------------------------------------------
// C[m,n] = sA[m]*sB[n]*(S0 + S1/128) + bias, S0 = q1a.q1b, S1 = q1a.q2b + q2a.q1b
// Block 128x128, 512 thr, 16 warps (8m x 2n), warp tile 16x64, K-tile 32.
// smem per stage 16KB: [tensor(Aq1,Aq2,Bq1,Bq2):4096][half:2048][row:16B]
// MODE 0: plain, MODE 1: qkv scatter, MODE 2: residual add.
#define SSTG 16384
#define GEMM_SMEM (3 * SSTG)

template<int MODE>
__global__ void __launch_bounds__(512) gemm_s8(
    const int8_t* __restrict__ Aq1, const int8_t* __restrict__ Aq2,
    const int8_t* __restrict__ Bq1, const int8_t* __restrict__ Bq2,
    const float* __restrict__ sA, const float* __restrict__ sB,
    const float* __restrict__ bias, const float* __restrict__ res,
    float* __restrict__ C)
{
    extern __shared__ char sm[];
    const uint32_t sbase = smem_u32(sm);
    const int tid = threadIdx.x, lane = tid & 31, wid = tid >> 5;
    const int g4 = lane >> 2, t4 = lane & 3;
    const int bm = blockIdx.y * 128, bn = blockIdx.x * 128;
    const int wm = (wid >> 1) * 16, wn = (wid & 1) * 64;

    int S0[8][4], S1[8][4];
    #pragma unroll
    for (int nt = 0; nt < 8; nt++)
        #pragma unroll
        for (int c = 0; c < 4; c++) { S0[nt][c] = 0; S1[nt][c] = 0; }

    auto load_stage = [&](int slot, int k0) {
        #pragma unroll
        for (int j = 0; j < 2; j++) {
            int c = tid + j * 512;
            int tensor = c >> 8, idx = c & 255;
            int half = idx >> 7, row = idx & 127;
            const int8_t* gp = (tensor == 0) ? Aq1 : (tensor == 1) ? Aq2
                             : (tensor == 2) ? Bq1 : Bq2;
            int rb = (tensor < 2) ? bm : bn;
            cpa16(sbase + slot * SSTG + tensor * 4096 + half * 2048 + row * 16,
                  gp + (size_t)(rb + row) * KP + k0 + half * 16);
        }
    };

    load_stage(0, 0);  CP_COMMIT();
    load_stage(1, 32); CP_COMMIT();

    for (int i = 0; i < 32; i++) {
        if (i < 31) { CP_WAIT(1); } else { CP_WAIT(0); }
        __syncthreads();
        if (i + 2 < 32) { load_stage((i + 2) % 3, (i + 2) * 32); CP_COMMIT(); }

        const char* st = sm + (i % 3) * SSTG;
        uint32_t a1[4], a2[4];
        {
            const char* ar = st + (wm + g4) * 16 + t4 * 4;
            a1[0] = *(const uint32_t*)(ar);
            a1[1] = *(const uint32_t*)(ar + 128);           // row +8
            a1[2] = *(const uint32_t*)(ar + 2048);          // k half 1
            a1[3] = *(const uint32_t*)(ar + 2048 + 128);
            a2[0] = *(const uint32_t*)(ar + 4096);
            a2[1] = *(const uint32_t*)(ar + 4096 + 128);
            a2[2] = *(const uint32_t*)(ar + 4096 + 2048);
            a2[3] = *(const uint32_t*)(ar + 4096 + 2048 + 128);
        }
        #pragma unroll
        for (int nt = 0; nt < 8; nt++) {
            const char* br = st + 8192 + (wn + nt * 8 + g4) * 16 + t4 * 4;
            uint32_t b10 = *(const uint32_t*)(br);
            uint32_t b11 = *(const uint32_t*)(br + 2048);
            uint32_t b20 = *(const uint32_t*)(br + 4096);
            uint32_t b21 = *(const uint32_t*)(br + 4096 + 2048);
            MMA_S8(S0[nt], a1, b10, b11);
            MMA_S8(S1[nt], a1, b20, b21);
            MMA_S8(S1[nt], a2, b10, b11);
        }
    }

    // epilogue
    #pragma unroll
    for (int nt = 0; nt < 8; nt++) {
        const int m0 = bm + wm + g4;
        const int n0 = bn + wn + nt * 8 + t4 * 2;
        const float sb0 = sB[n0], sb1 = sB[n0 + 1];
        const float bi0 = bias[n0], bi1 = bias[n0 + 1];
        #pragma unroll
        for (int r = 0; r < 2; r++) {
            const int m = m0 + r * 8;
            const float sa_ = sA[m];
            float v0 = sa_ * sb0 * ((float)S0[nt][r*2]   + (float)S1[nt][r*2]   * 0.0078125f) + bi0;
            float v1 = sa_ * sb1 * ((float)S0[nt][r*2+1] + (float)S1[nt][r*2+1] * 0.0078125f) + bi1;
            if (MODE == 0) {
                *(float2*)&C[(size_t)m * 1024 + n0] = make_float2(v0, v1);
            } else if (MODE == 1) {
                int bb = m >> 10, s = m & 1023, h = n0 >> 6, d = n0 & 63;
                *(float2*)&C[(size_t)(((bb << 4) + h) * 1024 + s) * 64 + d] =
                    make_float2(v0, v1);
            } else {
                const float2 rr = *(const float2*)&res[(size_t)m * 1024 + n0];
                *(float2*)&C[(size_t)m * 1024 + n0] = make_float2(rr.x + v0, rr.y + v1);
            }
        }
    }
}

// ---------------- final decode -----------------------------------------------
__global__ void __launch_bounds__(512) dec_k(
    const float* __restrict__ x2, const float* __restrict__ w,
    const float* __restrict__ bias, float* __restrict__ out)
{
    const int m = blockIdx.x;
    const int b = m >> 10, s = m & 1023;
    const int n = threadIdx.x >> 5;
    const int lane = threadIdx.x & 31;
    const float4* xr = (const float4*)(x2 + (size_t)m * FDEC);
    const float4* wr = (const float4*)(w  + (size_t)n * FDEC);
    float sum = 0.f;
    #pragma unroll
    for (int i = 0; i < 8; i++) {
        float4 a  = xr[lane + i * 32];
        float4 ww = wr[lane + i * 32];
        sum += a.x * ww.x + a.y * ww.y + a.z * ww.z + a.w * ww.w;
    }
    #pragma unroll
    for (int o = 16; o; o >>= 1) sum += __shfl_xor_sync(0xffffffffu, sum, o);
    if (lane == 0)
        out[(size_t)(b * FD + n) * NS + s] = sum + bias[n];
}

// ---------------- tf32 mma flash attention with ALiBi ------------------------
#define ASTR 68
#define ATTN_SMEM (3 * 64 * ASTR * (int)sizeof(float))

__global__ void __launch_bounds__(128) attn_tc(
    const float* __restrict__ q, const float* __restrict__ k,
    const float* __restrict__ v, float* __restrict__ o)
{
    extern __shared__ float smf[];
    float* Ks = smf;
    float* Vs = Ks + 64 * ASTR;
    float* Ps = Vs + 64 * ASTR;

    const int qc = blockIdx.x, h = blockIdx.y, b = blockIdx.z;
    const int tid = threadIdx.x, lane = tid & 31, w = tid >> 5;
    const int g4 = lane >> 2, t4 = lane & 3;

    const size_t head = (size_t)(b * NH + h) * NS * NDK;
    const float* qb = q + head;
    const float* kb = k + head;
    const float* vb = v + head;

    uint32_t qa[8][4];
    {
        const int r0 = qc * 64 + w * 16 + g4;
        #pragma unroll
        for (int kk = 0; kk < 8; kk++) {
            int c0 = kk * 8 + t4;
            qa[kk][0] = to_tf32(qb[(size_t)r0 * 64 + c0] * 0.125f);
            qa[kk][1] = to_tf32(qb[(size_t)(r0 + 8) * 64 + c0] * 0.125f);
            qa[kk][2] = to_tf32(qb[(size_t)r0 * 64 + c0 + 4] * 0.125f);
            qa[kk][3] = to_tf32(qb[(size_t)(r0 + 8) * 64 + c0 + 4] * 0.125f);
        }
    }

    const float slope = exp2f(-0.5f * (float)(h + 1));
    float oacc[8][4];
    #pragma unroll
    for (int dt = 0; dt < 8; dt++)
        #pragma unroll
        for (int c = 0; c < 4; c++) oacc[dt][c] = 0.f;
    float mrow[2] = { -1e30f, -1e30f };
    float lrow[2] = { 0.f, 0.f };

    const int lrow_ld = tid >> 1, lcol0 = (tid & 1) * 32;

    for (int kc = 0; kc <= qc; kc++) {
        {
            const float* ksrc = kb + (size_t)(kc * 64 + lrow_ld) * 64 + lcol0;
            const float* vsrc = vb + (size_t)(kc * 64 + lrow_ld) * 64 + lcol0;
            float* kd = Ks + lrow_ld * ASTR + lcol0;
            #pragma unroll
            for (int c = 0; c < 32; c += 4) {
                float4 t = *(const float4*)(ksrc + c);
                *(float4*)(kd + c) = t;
                float4 tv = *(const float4*)(vsrc + c);
                Vs[(lcol0 + c + 0) * ASTR + lrow_ld] = tv.x;
                Vs[(lcol0 + c + 1) * ASTR + lrow_ld] = tv.y;
                Vs[(lcol0 + c + 2) * ASTR + lrow_ld] = tv.z;
                Vs[(lcol0 + c + 3) * ASTR + lrow_ld] = tv.w;
            }
        }
        __syncthreads();

        float sc[8][4];
        #pragma unroll
        for (int nt = 0; nt < 8; nt++) {
            sc[nt][0] = sc[nt][1] = sc[nt][2] = sc[nt][3] = 0.f;
            #pragma unroll
            for (int kk = 0; kk < 8; kk++) {
                const float* kp = &Ks[(nt * 8 + g4) * ASTR + kk * 8 + t4];
                uint32_t b0 = to_tf32(kp[0]);
                uint32_t b1 = to_tf32(kp[4]);
                MMA_TF32(sc[nt], qa[kk], b0, b1);
            }
        }

        const bool diag = (kc == qc);
        #pragma unroll
        for (int half = 0; half < 2; half++) {
            const int wr = w * 16 + g4 + half * 8;
            const int ig = qc * 64 + wr;
            float mx = -1e30f;
            #pragma unroll
            for (int nt = 0; nt < 8; nt++) {
                #pragma unroll
                for (int e = 0; e < 2; e++) {
                    int jl = nt * 8 + t4 * 2 + e;
                    int jg = kc * 64 + jl;
                    float val = sc[nt][half * 2 + e] + slope * (float)jg;
                    if (diag && jg > ig) val -= 1e9f;
                    sc[nt][half * 2 + e] = val;
                    mx = fmaxf(mx, val);
                }
            }
            mx = fmaxf(mx, __shfl_xor_sync(0xffffffffu, mx, 1));
            mx = fmaxf(mx, __shfl_xor_sync(0xffffffffu, mx, 2));
            float mnew = fmaxf(mrow[half], mx);
            float corr = __expf(mrow[half] - mnew);
            mrow[half] = mnew;
            float rs = 0.f;
            #pragma unroll
            for (int nt = 0; nt < 8; nt++) {
                #pragma unroll
                for (int e = 0; e < 2; e++) {
                    float p = __expf(sc[nt][half * 2 + e] - mnew);
                    rs += p;
                    Ps[wr * ASTR + nt * 8 + t4 * 2 + e] = p;
                }
            }
            rs += __shfl_xor_sync(0xffffffffu, rs, 1);
            rs += __shfl_xor_sync(0xffffffffu, rs, 2);
            lrow[half] = lrow[half] * corr + rs;
            #pragma unroll
            for (int dt = 0; dt < 8; dt++) {
                oacc[dt][half * 2]     *= corr;
                oacc[dt][half * 2 + 1] *= corr;
            }
        }
        __syncwarp();

        #pragma unroll
        for (int kk = 0; kk < 8; kk++) {
            uint32_t pa[4];
            const int pr = w * 16 + g4;
            pa[0] = to_tf32(Ps[pr * ASTR + kk * 8 + t4]);
            pa[1] = to_tf32(Ps[(pr + 8) * ASTR + kk * 8 + t4]);
            pa[2] = to_tf32(Ps[pr * ASTR + kk * 8 + t4 + 4]);
            pa[3] = to_tf32(Ps[(pr + 8) * ASTR + kk * 8 + t4 + 4]);
            #pragma unroll
            for (int dt = 0; dt < 8; dt++) {
                const float* vp = &Vs[(dt * 8 + g4) * ASTR + kk * 8 + t4];
                uint32_t b0 = to_tf32(vp[0]);
                uint32_t b1 = to_tf32(vp[4]);
                MMA_TF32(oacc[dt], pa, b0, b1);
            }
        }
        __syncthreads();
    }

    #pragma unroll
    for (int half = 0; half < 2; half++) {
        const int sg = qc * 64 + w * 16 + g4 + half * 8;
        const float inv = 1.0f / lrow[half];
        const size_t base = (size_t)(b * NS + sg) * (NH * NDK) + h * NDK;
        #pragma unroll
        for (int dt = 0; dt < 8; dt++) {
            int d = dt * 8 + t4 * 2;
            float v0 = oacc[dt][half * 2]     * inv;
            float v1 = oacc[dt][half * 2 + 1] * inv;
            *(float2*)&o[base + d] = make_float2(v0, v1);
        }
    }
}

// ---------------- launcher ----------------------------------------------------
extern "C" void kernel_launch(void* const* d_in, const int* in_sizes, int n_in,
                              void* d_out, int out_size)
{
    const float* z   = (const float*)d_in[0];
    const float* r   = (const float*)d_in[1];
    const float* dwn = (const float*)d_in[2];
    const float* dbn = (const float*)d_in[3];
    const float* lng = (const float*)d_in[4];
    const float* lnb = (const float*)d_in[5];
    const float* wq  = (const float*)d_in[6];
    const float* bq  = (const float*)d_in[7];
    const float* wk  = (const float*)d_in[8];
    const float* bk  = (const float*)d_in[9];
    const float* wv  = (const float*)d_in[10];
    const float* bv  = (const float*)d_in[11];
    const float* wo  = (const float*)d_in[12];
    const float* bo  = (const float*)d_in[13];
    const float* dcw = (const float*)d_in[14];
    const float* dcb = (const float*)d_in[15];
    float* out = (float*)d_out;

    float *x, *q, *k, *v, *o, *x2;
    int8_t *xc1, *xc2, *xn1, *xn2, *oq1, *oq2;
    int8_t *wd1, *wd2, *wq1, *wq2, *wk1, *wk2, *wv1, *wv2, *wo1, *wo2;
    float *sxc, *sxn, *so, *swd, *swq, *swk, *swv, *swo;
    cudaGetSymbolAddress((void**)&x,  g_x);
    cudaGetSymbolAddress((void**)&q,  g_q);
    cudaGetSymbolAddress((void**)&k,  g_k);
    cudaGetSymbolAddress((void**)&v,  g_v);
    cudaGetSymbolAddress((void**)&o,  g_o);
    cudaGetSymbolAddress((void**)&x2, g_x2);
    cudaGetSymbolAddress((void**)&xc1, g_xc1); cudaGetSymbolAddress((void**)&xc2, g_xc2);
    cudaGetSymbolAddress((void**)&xn1, g_xn1); cudaGetSymbolAddress((void**)&xn2, g_xn2);
    cudaGetSymbolAddress((void**)&oq1, g_oq1); cudaGetSymbolAddress((void**)&oq2, g_oq2);
    cudaGetSymbolAddress((void**)&wd1, g_wd1); cudaGetSymbolAddress((void**)&wd2, g_wd2);
    cudaGetSymbolAddress((void**)&wq1, g_wq1); cudaGetSymbolAddress((void**)&wq2, g_wq2);
    cudaGetSymbolAddress((void**)&wk1, g_wk1); cudaGetSymbolAddress((void**)&wk2, g_wk2);
    cudaGetSymbolAddress((void**)&wv1, g_wv1); cudaGetSymbolAddress((void**)&wv2, g_wv2);
    cudaGetSymbolAddress((void**)&wo1, g_wo1); cudaGetSymbolAddress((void**)&wo2, g_wo2);
    cudaGetSymbolAddress((void**)&sxc, g_sxc); cudaGetSymbolAddress((void**)&sxn, g_sxn);
    cudaGetSymbolAddress((void**)&so,  g_so);
    cudaGetSymbolAddress((void**)&swd, g_swd); cudaGetSymbolAddress((void**)&swq, g_swq);
    cudaGetSymbolAddress((void**)&swk, g_swk); cudaGetSymbolAddress((void**)&swv, g_swv);
    cudaGetSymbolAddress((void**)&swo, g_swo);

    cudaFuncSetAttribute(gemm_s8<0>, cudaFuncAttributeMaxDynamicSharedMemorySize, GEMM_SMEM);
    cudaFuncSetAttribute(gemm_s8<1>, cudaFuncAttributeMaxDynamicSharedMemorySize, GEMM_SMEM);
    cudaFuncSetAttribute(gemm_s8<2>, cudaFuncAttributeMaxDynamicSharedMemorySize, GEMM_SMEM);
    cudaFuncSetAttribute(attn_tc,    cudaFuncAttributeMaxDynamicSharedMemorySize, ATTN_SMEM);

    // quantize inputs + weights
    concat_quant_k<<<MROWS, 256>>>(r, z, xc1, xc2, sxc);
    quant_k<<<FDEC, 256>>>(dwn, KINR, wd1, wd2, swd);
    quant_k<<<FDEC, 256>>>(wq, FDEC, wq1, wq2, swq);
    quant_k<<<FDEC, 256>>>(wk, FDEC, wk1, wk2, swk);
    quant_k<<<FDEC, 256>>>(wv, FDEC, wv1, wv2, swv);
    quant_k<<<FDEC, 256>>>(wo, FDEC, wo1, wo2, swo);

    dim3 ggrid(8, 64);
    // dense
    gemm_s8<0><<<ggrid, 512, GEMM_SMEM>>>(xc1, xc2, wd1, wd2, sxc, swd, dbn, nullptr, x);
    // LN + quant
    ln_quant_k<<<MROWS, 256>>>(x, lng, lnb, xn1, xn2, sxn);
    // QKV
    gemm_s8<1><<<ggrid, 512, GEMM_SMEM>>>(xn1, xn2, wq1, wq2, sxn, swq, bq, nullptr, q);
    gemm_s8<1><<<ggrid, 512, GEMM_SMEM>>>(xn1, xn2, wk1, wk2, sxn, swk, bk, nullptr, k);
    gemm_s8<1><<<ggrid, 512, GEMM_SMEM>>>(xn1, xn2, wv1, wv2, sxn, swv, bv, nullptr, v);
    // attention
    attn_tc<<<dim3(NS / 64, NH, NB), 128, ATTN_SMEM>>>(q, k, v, o);
    // quantize o, out projection + residual
    quant_k<<<MROWS, 256>>>(o, FDEC, oq1, oq2, so);
    gemm_s8<2><<<ggrid, 512, GEMM_SMEM>>>(oq1, oq2, wo1, wo2, so, swo, bo, x, x2);
    // decode + transpose
    dec_k<<<MROWS, 512>>>(x2, dcw, dcb, out);
}

// round 10
// speedup vs baseline: 1.0843x; 1.0843x over previous
#include <cuda_runtime.h>
#include <cuda_bf16.h>
#include <cstdint>
#include <math.h>

// Problem dims (fixed)
#define NB   8
#define NS   1024
#define NH   16
#define NDK  64
#define FDEC 1024
#define FD   16
#define KINR 784
#define KP   1024
#define MROWS (NB*NS)   // 8192

// ---------------- scratch (static __device__, no allocation) ----------------
__device__ float g_xcat[MROWS * KP];     // concat input, tf32-rounded
__device__ float g_x   [MROWS * FDEC];   // dense output (residual, full fp32)
__device__ float g_xn  [MROWS * FDEC];   // LN output, tf32-rounded
__device__ float g_q   [MROWS * FDEC];
__device__ float g_k   [MROWS * FDEC];
__device__ float g_v   [MROWS * FDEC];
__device__ float g_o   [MROWS * FDEC];   // attention out, tf32-rounded
__device__ float g_x2  [MROWS * FDEC];
__device__ float g_wd  [FDEC * KP];      // rounded/padded weights
__device__ float g_wqr [FDEC * KP];
__device__ float g_wkr [FDEC * KP];
__device__ float g_wvr [FDEC * KP];
__device__ float g_wor [FDEC * KP];

// ---------------- PTX helpers ------------------------------------------------
__device__ __forceinline__ uint32_t smem_u32(const void* p) {
    uint32_t a;
    asm("{ .reg .u64 t; cvta.to.shared.u64 t, %1; cvt.u32.u64 %0, t; }" : "=r"(a) : "l"(p));
    return a;
}

#define LDSM4(R, A) \
    asm volatile("ldmatrix.sync.aligned.m8n8.x4.shared.b16 {%0,%1,%2,%3}, [%4];" \
        : "=r"((R)[0]), "=r"((R)[1]), "=r"((R)[2]), "=r"((R)[3]) : "r"(A))

#define MMA_TF32(C, A, B0, B1) \
    asm volatile("mma.sync.aligned.m16n8k8.row.col.f32.tf32.tf32.f32 " \
        "{%0,%1,%2,%3},{%4,%5,%6,%7},{%8,%9},{%0,%1,%2,%3};" \
        : "+f"((C)[0]), "+f"((C)[1]), "+f"((C)[2]), "+f"((C)[3]) \
        : "r"((A)[0]), "r"((A)[1]), "r"((A)[2]), "r"((A)[3]), "r"(B0), "r"(B1))

__device__ __forceinline__ uint32_t to_tf32(float f) {
    uint32_t r;
    asm("cvt.rna.tf32.f32 %0, %1;" : "=r"(r) : "f"(f));
    return r;
}
__device__ __forceinline__ float tf32r(float f) {
    return __uint_as_float(to_tf32(f));
}

__device__ __forceinline__ void cpa16(uint32_t dst, const void* src) {
    asm volatile("cp.async.cg.shared.global [%0], [%1], 16;" :: "r"(dst), "l"(src));
}
#define CP_COMMIT() asm volatile("cp.async.commit_group;" ::: "memory")
#define CP_WAIT(n)  asm volatile("cp.async.wait_group %0;" :: "n"(n) : "memory")

// ---------------- producers (tf32-rounded outputs) ---------------------------
__global__ void __launch_bounds__(256) concat_k(
    const float* __restrict__ r, const float* __restrict__ z,
    float* __restrict__ xcat)
{
    int idx = blockIdx.x * 256 + threadIdx.x;
    if (idx >= MROWS * KP) return;
    int m = idx >> 10, f = idx & 1023;
    float v = (f < 16) ? r[m * 16 + f]
            : (f < KINR) ? z[(m >> 10) * 768 + (f - 16)] : 0.f;
    xcat[idx] = tf32r(v);
}

// weight round + pad: w [1024, Ksrc] -> tf32-rounded [1024, 1024]
__global__ void __launch_bounds__(256) roundpad_k(
    const float* __restrict__ w, int Ksrc, float* __restrict__ dst)
{
    int idx = blockIdx.x * 256 + threadIdx.x;
    if (idx >= FDEC * KP) return;
    int n = idx >> 10, k = idx & 1023;
    dst[idx] = (k < Ksrc) ? tf32r(w[n * Ksrc + k]) : 0.f;
}

// ---------------- LayerNorm (fp32 in, tf32-rounded out) ----------------------
__device__ __forceinline__ float blockReduce(float val, float* sh)
{
    __syncthreads();
    int lane = threadIdx.x & 31, wid = threadIdx.x >> 5;
    #pragma unroll
    for (int o = 16; o; o >>= 1) val += __shfl_xor_sync(0xffffffffu, val, o);
    if (lane == 0) sh[wid] = val;
    __syncthreads();
    if (wid == 0) {
        val = (lane < 8) ? sh[lane] : 0.f;
        #pragma unroll
        for (int o = 4; o; o >>= 1) val += __shfl_xor_sync(0xffffffffu, val, o);
        if (lane == 0) sh[0] = val;
    }
    __syncthreads();
    return sh[0];
}

__global__ void __launch_bounds__(256) ln_k(
    const float* __restrict__ x, const float* __restrict__ g,
    const float* __restrict__ beta, float* __restrict__ xn)
{
    __shared__ float red[32];
    int row = blockIdx.x;
    float4 v = ((const float4*)(x + (size_t)row * 1024))[threadIdx.x];
    float s = blockReduce(v.x + v.y + v.z + v.w, red);
    float mean = s * (1.0f / 1024.0f);
    float dx = v.x - mean, dy = v.y - mean, dz = v.z - mean, dw = v.w - mean;
    float s2 = blockReduce(dx*dx + dy*dy + dz*dz + dw*dw, red);
    float inv = rsqrtf(s2 * (1.0f / 1024.0f) + 1e-6f);
    float4 gg = ((const float4*)g)[threadIdx.x];
    float4 bb = ((const float4*)beta)[threadIdx.x];
    float4 o;
    o.x = tf32r(gg.x * dx * inv + bb.x);
    o.y = tf32r(gg.y * dy * inv + bb.y);
    o.z = tf32r(gg.z * dz * inv + bb.z);
    o.w = tf32r(gg.w * dw * inv + bb.w);
    ((float4*)(xn + (size_t)row * 1024))[threadIdx.x] = o;
}

// ---------------- tf32 mma GEMM with ldmatrix fragments ----------------------
// C[M,1024] = A[M,1024] @ W[1024,1024]^T + bias. Operands pre-rounded to tf32
// in global, so no cvt in the hot loop; ldmatrix.x4 on f32-as-b16 tiles gives
// the tf32 m16n8k8 fragments directly.
// Block 128x128, 256 thr (8 warps, 4m x 2n), warp tile 32x64, K-tile 32,
// 3-stage cp.async. MODE 0: plain, MODE 1: qkv scatter, MODE 2: residual add.
#define GSTR  36                          // smem row stride, floats
#define TILE_BYTES (128 * GSTR * 4)       // 18432
#define STAGE_B (2 * TILE_BYTES)          // 36864
#define GEMM_SMEM (3 * STAGE_B)           // 110592

template<int MODE>
__global__ void __launch_bounds__(256) gemm_tf32(
    const float* __restrict__ A, const float* __restrict__ Bw,
    const float* __restrict__ bias, const float* __restrict__ res,
    float* __restrict__ C)
{
    extern __shared__ char sm[];
    const uint32_t sbase = smem_u32(sm);
    const int tid = threadIdx.x, lane = tid & 31, wid = tid >> 5;
    const int g4 = lane >> 2, t4 = lane & 3;
    const int bm = blockIdx.y * 128, bn = blockIdx.x * 128;
    const int wm = (wid & 3) * 32, wn = (wid >> 2) * 64;

    float acc[2][8][4];
    #pragma unroll
    for (int a = 0; a < 2; a++)
        #pragma unroll
        for (int b = 0; b < 8; b++)
            #pragma unroll
            for (int c = 0; c < 4; c++) acc[a][b][c] = 0.f;

    // ldmatrix per-thread byte offsets within a stage
    // A: matrix0 rows wm+0-7 cols 0-3, m1 rows+8, m2 cols+4, m3 rows+8 cols+4
    const uint32_t aoff =
        ((uint32_t)(wm + (lane & 7) + ((lane >> 3) & 1) * 8) * GSTR
         + ((lane >> 4) << 2)) * 4;
    // B: matrix j = cols j*4 (kk pairs), rows wn+nt*8+(lane&7)
    const uint32_t boff =
        ((uint32_t)(wn + (lane & 7)) * GSTR + ((lane >> 3) & 3) * 4) * 4;

    auto load_stage = [&](int slot, int k0) {
        const uint32_t sa = sbase + slot * STAGE_B;
        #pragma unroll
        for (int c = 0; c < 4; c++) {
            int chunk = tid + c * 256;
            int row = chunk >> 3, seg = chunk & 7;
            cpa16(sa + row * (GSTR*4) + seg * 16,
                  A + (size_t)(bm + row) * KP + k0 + seg * 4);
        }
        const uint32_t sb = sa + TILE_BYTES;
        #pragma unroll
        for (int c = 0; c < 4; c++) {
            int chunk = tid + c * 256;
            int row = chunk >> 3, seg = chunk & 7;
            cpa16(sb + row * (GSTR*4) + seg * 16,
                  Bw + (size_t)(bn + row) * KP + k0 + seg * 4);
        }
    };

    load_stage(0, 0);  CP_COMMIT();
    load_stage(1, 32); CP_COMMIT();

    for (int i = 0; i < 32; i++) {
        if (i < 31) { CP_WAIT(1); } else { CP_WAIT(0); }
        __syncthreads();
        if (i + 2 < 32) { load_stage((i + 2) % 3, (i + 2) * 32); CP_COMMIT(); }

        const uint32_t As = sbase + (i % 3) * STAGE_B;
        const uint32_t Bs = As + TILE_BYTES;

        // A fragments: [kk][am][4]
        uint32_t a[4][2][4];
        #pragma unroll
        for (int kk = 0; kk < 4; kk++)
            #pragma unroll
            for (int am = 0; am < 2; am++)
                LDSM4(a[kk][am], As + aoff + am * (16 * GSTR * 4) + kk * 32);

        #pragma unroll
        for (int nt = 0; nt < 8; nt++) {
            uint32_t b01[4], b23[4];
            const uint32_t bb = Bs + boff + nt * (8 * GSTR * 4);
            LDSM4(b01, bb);          // {b0k0, b1k0, b0k1, b1k1}
            LDSM4(b23, bb + 64);     // {b0k2, b1k2, b0k3, b1k3}
            MMA_TF32(acc[0][nt], a[0][0], b01[0], b01[1]);
            MMA_TF32(acc[1][nt], a[0][1], b01[0], b01[1]);
            MMA_TF32(acc[0][nt], a[1][0], b01[2], b01[3]);
            MMA_TF32(acc[1][nt], a[1][1], b01[2], b01[3]);
            MMA_TF32(acc[0][nt], a[2][0], b23[0], b23[1]);
            MMA_TF32(acc[1][nt], a[2][1], b23[0], b23[1]);
            MMA_TF32(acc[0][nt], a[3][0], b23[2], b23[3]);
            MMA_TF32(acc[1][nt], a[3][1], b23[2], b23[3]);
        }
    }

    // epilogue: acc[am][nt]: m = bm+wm+am*16+g4 (+8), n = bn+wn+nt*8+t4*2 (+1)
    #pragma unroll
    for (int am = 0; am < 2; am++) {
        #pragma unroll
        for (int nt = 0; nt < 8; nt++) {
            int mrow = bm + wm + am * 16 + g4;
            int ncol = bn + wn + nt * 8 + t4 * 2;
            float b0 = bias[ncol], b1 = bias[ncol + 1];
            #pragma unroll
            for (int r = 0; r < 2; r++) {
                int m = mrow + r * 8;
                float v0 = acc[am][nt][r * 2]     + b0;
                float v1 = acc[am][nt][r * 2 + 1] + b1;
                if (MODE == 0) {
                    *(float2*)&C[(size_t)m * 1024 + ncol] = make_float2(v0, v1);
                } else if (MODE == 1) {
                    int bb = m >> 10, s = m & 1023, h = ncol >> 6, d = ncol & 63;
                    *(float2*)&C[(size_t)(((bb << 4) + h) * 1024 + s) * 64 + d] =
                        make_float2(v0, v1);
                } else {
                    const float2 rr = *(const float2*)&res[(size_t)m * 1024 + ncol];
                    *(float2*)&C[(size_t)m * 1024 + ncol] =
                        make_float2(rr.x + v0, rr.y + v1);
                }
            }
        }
    }
}

// ---------------- final decode -----------------------------------------------
__global__ void __launch_bounds__(512) dec_k(
    const float* __restrict__ x2, const float* __restrict__ w,
    const float* __restrict__ bias, float* __restrict__ out)
{
    const int m = blockIdx.x;
    const int b = m >> 10, s = m & 1023;
    const int n = threadIdx.x >> 5;
    const int lane = threadIdx.x & 31;
    const float4* xr = (const float4*)(x2 + (size_t)m * FDEC);
    const float4* wr = (const float4*)(w  + (size_t)n * FDEC);
    float sum = 0.f;
    #pragma unroll
    for (int i = 0; i < 8; i++) {
        float4 a  = xr[lane + i * 32];
        float4 ww = wr[lane + i * 32];
        sum += a.x * ww.x + a.y * ww.y + a.z * ww.z + a.w * ww.w;
    }
    #pragma unroll
    for (int o = 16; o; o >>= 1) sum += __shfl_xor_sync(0xffffffffu, sum, o);
    if (lane == 0)
        out[(size_t)(b * FD + n) * NS + s] = sum + bias[n];
}

// ---------------- tf32 mma flash attention with ALiBi ------------------------
#define ASTR 68
#define ATTN_SMEM (3 * 64 * ASTR * (int)sizeof(float))

__global__ void __launch_bounds__(128) attn_tc(
    const float* __restrict__ q, const float* __restrict__ k,
    const float* __restrict__ v, float* __restrict__ o)
{
    extern __shared__ float smf[];
    float* Ks = smf;
    float* Vs = Ks + 64 * ASTR;
    float* Ps = Vs + 64 * ASTR;

    const int qc = blockIdx.x, h = blockIdx.y, b = blockIdx.z;
    const int tid = threadIdx.x, lane = tid & 31, w = tid >> 5;
    const int g4 = lane >> 2, t4 = lane & 3;

    const size_t head = (size_t)(b * NH + h) * NS * NDK;
    const float* qb = q + head;
    const float* kb = k + head;
    const float* vb = v + head;

    uint32_t qa[8][4];
    {
        const int r0 = qc * 64 + w * 16 + g4;
        #pragma unroll
        for (int kk = 0; kk < 8; kk++) {
            int c0 = kk * 8 + t4;
            qa[kk][0] = to_tf32(qb[(size_t)r0 * 64 + c0] * 0.125f);
            qa[kk][1] = to_tf32(qb[(size_t)(r0 + 8) * 64 + c0] * 0.125f);
            qa[kk][2] = to_tf32(qb[(size_t)r0 * 64 + c0 + 4] * 0.125f);
            qa[kk][3] = to_tf32(qb[(size_t)(r0 + 8) * 64 + c0 + 4] * 0.125f);
        }
    }

    const float slope = exp2f(-0.5f * (float)(h + 1));
    float oacc[8][4];
    #pragma unroll
    for (int dt = 0; dt < 8; dt++)
        #pragma unroll
        for (int c = 0; c < 4; c++) oacc[dt][c] = 0.f;
    float mrow[2] = { -1e30f, -1e30f };
    float lrow[2] = { 0.f, 0.f };

    const int lrow_ld = tid >> 1, lcol0 = (tid & 1) * 32;

    for (int kc = 0; kc <= qc; kc++) {
        {
            const float* ksrc = kb + (size_t)(kc * 64 + lrow_ld) * 64 + lcol0;
            const float* vsrc = vb + (size_t)(kc * 64 + lrow_ld) * 64 + lcol0;
            float* kd = Ks + lrow_ld * ASTR + lcol0;
            #pragma unroll
            for (int c = 0; c < 32; c += 4) {
                float4 t = *(const float4*)(ksrc + c);
                *(float4*)(kd + c) = t;
                float4 tv = *(const float4*)(vsrc + c);
                Vs[(lcol0 + c + 0) * ASTR + lrow_ld] = tv.x;
                Vs[(lcol0 + c + 1) * ASTR + lrow_ld] = tv.y;
                Vs[(lcol0 + c + 2) * ASTR + lrow_ld] = tv.z;
                Vs[(lcol0 + c + 3) * ASTR + lrow_ld] = tv.w;
            }
        }
        __syncthreads();

        float sc[8][4];
        #pragma unroll
        for (int nt = 0; nt < 8; nt++) {
            sc[nt][0] = sc[nt][1] = sc[nt][2] = sc[nt][3] = 0.f;
            #pragma unroll
            for (int kk = 0; kk < 8; kk++) {
                const float* kp = &Ks[(nt * 8 + g4) * ASTR + kk * 8 + t4];
                uint32_t b0 = to_tf32(kp[0]);
                uint32_t b1 = to_tf32(kp[4]);
                MMA_TF32(sc[nt], qa[kk], b0, b1);
            }
        }

        const bool diag = (kc == qc);
        #pragma unroll
        for (int half = 0; half < 2; half++) {
            const int wr = w * 16 + g4 + half * 8;
            const int ig = qc * 64 + wr;
            float mx = -1e30f;
            #pragma unroll
            for (int nt = 0; nt < 8; nt++) {
                #pragma unroll
                for (int e = 0; e < 2; e++) {
                    int jl = nt * 8 + t4 * 2 + e;
                    int jg = kc * 64 + jl;
                    float val = sc[nt][half * 2 + e] + slope * (float)jg;
                    if (diag && jg > ig) val -= 1e9f;
                    sc[nt][half * 2 + e] = val;
                    mx = fmaxf(mx, val);
                }
            }
            mx = fmaxf(mx, __shfl_xor_sync(0xffffffffu, mx, 1));
            mx = fmaxf(mx, __shfl_xor_sync(0xffffffffu, mx, 2));
            float mnew = fmaxf(mrow[half], mx);
            float corr = __expf(mrow[half] - mnew);
            mrow[half] = mnew;
            float rs = 0.f;
            #pragma unroll
            for (int nt = 0; nt < 8; nt++) {
                #pragma unroll
                for (int e = 0; e < 2; e++) {
                    float p = __expf(sc[nt][half * 2 + e] - mnew);
                    rs += p;
                    Ps[wr * ASTR + nt * 8 + t4 * 2 + e] = p;
                }
            }
            rs += __shfl_xor_sync(0xffffffffu, rs, 1);
            rs += __shfl_xor_sync(0xffffffffu, rs, 2);
            lrow[half] = lrow[half] * corr + rs;
            #pragma unroll
            for (int dt = 0; dt < 8; dt++) {
                oacc[dt][half * 2]     *= corr;
                oacc[dt][half * 2 + 1] *= corr;
            }
        }
        __syncwarp();

        #pragma unroll
        for (int kk = 0; kk < 8; kk++) {
            uint32_t pa[4];
            const int pr = w * 16 + g4;
            pa[0] = to_tf32(Ps[pr * ASTR + kk * 8 + t4]);
            pa[1] = to_tf32(Ps[(pr + 8) * ASTR + kk * 8 + t4]);
            pa[2] = to_tf32(Ps[pr * ASTR + kk * 8 + t4 + 4]);
            pa[3] = to_tf32(Ps[(pr + 8) * ASTR + kk * 8 + t4 + 4]);
            #pragma unroll
            for (int dt = 0; dt < 8; dt++) {
                const float* vp = &Vs[(dt * 8 + g4) * ASTR + kk * 8 + t4];
                uint32_t b0 = to_tf32(vp[0]);
                uint32_t b1 = to_tf32(vp[4]);
                MMA_TF32(oacc[dt], pa, b0, b1);
            }
        }
        __syncthreads();
    }

    // epilogue: write tf32-rounded o to [B,S,H*DK] (o only feeds a GEMM)
    #pragma unroll
    for (int half = 0; half < 2; half++) {
        const int sg = qc * 64 + w * 16 + g4 + half * 8;
        const float inv = 1.0f / lrow[half];
        const size_t base = (size_t)(b * NS + sg) * (NH * NDK) + h * NDK;
        #pragma unroll
        for (int dt = 0; dt < 8; dt++) {
            int d = dt * 8 + t4 * 2;
            float v0 = tf32r(oacc[dt][half * 2]     * inv);
            float v1 = tf32r(oacc[dt][half * 2 + 1] * inv);
            *(float2*)&o[base + d] = make_float2(v0, v1);
        }
    }
}

// ---------------- launcher ----------------------------------------------------
extern "C" void kernel_launch(void* const* d_in, const int* in_sizes, int n_in,
                              void* d_out, int out_size)
{
    const float* z   = (const float*)d_in[0];
    const float* r   = (const float*)d_in[1];
    const float* dwn = (const float*)d_in[2];
    const float* dbn = (const float*)d_in[3];
    const float* lng = (const float*)d_in[4];
    const float* lnb = (const float*)d_in[5];
    const float* wq  = (const float*)d_in[6];
    const float* bq  = (const float*)d_in[7];
    const float* wk  = (const float*)d_in[8];
    const float* bk  = (const float*)d_in[9];
    const float* wv  = (const float*)d_in[10];
    const float* bv  = (const float*)d_in[11];
    const float* wo  = (const float*)d_in[12];
    const float* bo  = (const float*)d_in[13];
    const float* dcw = (const float*)d_in[14];
    const float* dcb = (const float*)d_in[15];
    float* out = (float*)d_out;

    float *xcat, *x, *xn, *q, *k, *v, *o, *x2;
    float *wd, *wqr, *wkr, *wvr, *wor;
    cudaGetSymbolAddress((void**)&xcat, g_xcat);
    cudaGetSymbolAddress((void**)&x,    g_x);
    cudaGetSymbolAddress((void**)&xn,   g_xn);
    cudaGetSymbolAddress((void**)&q,    g_q);
    cudaGetSymbolAddress((void**)&k,    g_k);
    cudaGetSymbolAddress((void**)&v,    g_v);
    cudaGetSymbolAddress((void**)&o,    g_o);
    cudaGetSymbolAddress((void**)&x2,   g_x2);
    cudaGetSymbolAddress((void**)&wd,   g_wd);
    cudaGetSymbolAddress((void**)&wqr,  g_wqr);
    cudaGetSymbolAddress((void**)&wkr,  g_wkr);
    cudaGetSymbolAddress((void**)&wvr,  g_wvr);
    cudaGetSymbolAddress((void**)&wor,  g_wor);

    cudaFuncSetAttribute(gemm_tf32<0>, cudaFuncAttributeMaxDynamicSharedMemorySize, GEMM_SMEM);
    cudaFuncSetAttribute(gemm_tf32<1>, cudaFuncAttributeMaxDynamicSharedMemorySize, GEMM_SMEM);
    cudaFuncSetAttribute(gemm_tf32<2>, cudaFuncAttributeMaxDynamicSharedMemorySize, GEMM_SMEM);
    cudaFuncSetAttribute(attn_tc,      cudaFuncAttributeMaxDynamicSharedMemorySize, ATTN_SMEM);

    const int WELTS = FDEC * KP;
    concat_k<<<(MROWS * KP + 255) / 256, 256>>>(r, z, xcat);
    roundpad_k<<<(WELTS + 255) / 256, 256>>>(dwn, KINR, wd);
    roundpad_k<<<(WELTS + 255) / 256, 256>>>(wq, FDEC, wqr);
    roundpad_k<<<(WELTS + 255) / 256, 256>>>(wk, FDEC, wkr);
    roundpad_k<<<(WELTS + 255) / 256, 256>>>(wv, FDEC, wvr);
    roundpad_k<<<(WELTS + 255) / 256, 256>>>(wo, FDEC, wor);

    dim3 ggrid(8, 64);
    gemm_tf32<0><<<ggrid, 256, GEMM_SMEM>>>(xcat, wd, dbn, nullptr, x);
    ln_k<<<MROWS, 256>>>(x, lng, lnb, xn);
    gemm_tf32<1><<<ggrid, 256, GEMM_SMEM>>>(xn, wqr, bq, nullptr, q);
    gemm_tf32<1><<<ggrid, 256, GEMM_SMEM>>>(xn, wkr, bk, nullptr, k);
    gemm_tf32<1><<<ggrid, 256, GEMM_SMEM>>>(xn, wvr, bv, nullptr, v);
    attn_tc<<<dim3(NS / 64, NH, NB), 128, ATTN_SMEM>>>(q, k, v, o);
    gemm_tf32<2><<<ggrid, 256, GEMM_SMEM>>>(o, wor, bo, x, x2);
    dec_k<<<MROWS, 512>>>(x2, dcw, dcb, out);
}